// round 10
// baseline (speedup 1.0000x reference)
#include <cuda_runtime.h>

#define TT 1024
#define OO 512
#define DD 256
#define HH 512

__device__ float g_ht[TT * HH];   // z_t @ W1[:D]            [1024,512]
__device__ float g_ho[OO * HH];   // z_o @ W1[D:] + b1       [512,512]
__device__ float g_ct[TT];        // 0.505 * <ht[t], W2>
__device__ float g_co[OO];        // 0.505 * <ho[o], W2> + b2

typedef unsigned long long u64;

__device__ __forceinline__ u64 add2(u64 a, u64 b) {
    u64 d; asm("add.rn.f32x2 %0,%1,%2;" : "=l"(d) : "l"(a), "l"(b)); return d;
}
__device__ __forceinline__ u64 fma2(u64 a, u64 b, u64 c) {
    u64 d; asm("fma.rn.f32x2 %0,%1,%2,%3;" : "=l"(d) : "l"(a), "l"(b), "l"(c)); return d;
}
__device__ __forceinline__ u64 dup2(float v) {
    u64 d; asm("mov.b64 %0,{%1,%1};" : "=l"(d) : "f"(v)); return d;
}

// ---------------------------------------------------------------------------
// Fused GEMM over combined M=1536: rows [0,1024)=z_t@W1[:D],
// [1024,1536)=z_o@W1[D:]+b1.
// BM=64, BN=128, BK=32, 256 threads (8 warps -> 2 warps/SMSP), micro 4m x 8n.
// Per warp-k: 1 LDS.128 (a, warp-broadcast) + 2 LDS.128 (b) + 4 dup movs
// + 16 FFMA2 -> fma-pipe-bound with 2 warps/SMSP hiding LDS latency.
// Double-buffered, 1 sync per 32-k block. Grid (4 n-tiles, 24 m-tiles) = 96.
// ---------------------------------------------------------------------------
__global__ __launch_bounds__(256) void gemm_kernel(
    const float* __restrict__ z_t, const float* __restrict__ z_o,
    const float* __restrict__ W1,  const float* __restrict__ b1)
{
    __shared__ float As[2][32][68];    // [buf][k][m]; 272B row (16B mult)
    __shared__ float Bs[2][32][132];   // [buf][k][n]; 528B row (16B mult)

    const int tid = threadIdx.x;
    const int mt  = blockIdx.y;             // 0..23
    const int n0  = blockIdx.x << 7;        // 0..384
    const bool isHo = (mt >= 16);
    const int m0 = (isHo ? (mt - 16) : mt) << 6;
    const float* A = isHo ? z_o : z_t;
    const float* B = isHo ? (W1 + (u64)DD * HH) : W1;
    float* C = isHo ? g_ho : g_ht;

    // A staging: m = tid&63, k-quarter = (tid>>6)*8, 2 float4 along k
    const int am  = tid & 63;
    const int akq = (tid >> 6) << 3;        // 0,8,16,24
    // B staging: brow = tid>>3 (0..31), bc = (tid&7)*16 floats, 4 float4 in n
    const int brow = tid >> 3;
    const int bc   = (tid & 7) << 4;

    // compute: n group of 8 at txg*8, m group of 4 at tyg*4
    const int txg = tid & 15;
    const int tyg = tid >> 4;               // 0..15

    u64 acc[4][4];                          // [m][n-pair]
    #pragma unroll
    for (int m = 0; m < 4; m++)
        #pragma unroll
        for (int j = 0; j < 4; j++) acc[m][j] = 0ull;

    const float* aptr = &A[(u64)(m0 + am) * DD + akq];
    const float* bptr = &B[(u64)brow * HH + n0 + bc];

    float4 va[2], vb[4];

    // ---- prologue: stage 0 ----
    va[0] = *reinterpret_cast<const float4*>(aptr);
    va[1] = *reinterpret_cast<const float4*>(aptr + 4);
    #pragma unroll
    for (int q = 0; q < 4; q++)
        vb[q] = *reinterpret_cast<const float4*>(bptr + (q << 2));

    As[0][akq + 0][am] = va[0].x; As[0][akq + 1][am] = va[0].y;
    As[0][akq + 2][am] = va[0].z; As[0][akq + 3][am] = va[0].w;
    As[0][akq + 4][am] = va[1].x; As[0][akq + 5][am] = va[1].y;
    As[0][akq + 6][am] = va[1].z; As[0][akq + 7][am] = va[1].w;
    #pragma unroll
    for (int q = 0; q < 4; q++)
        *reinterpret_cast<float4*>(&Bs[0][brow][bc + (q << 2)]) = vb[q];
    __syncthreads();

    #pragma unroll 1
    for (int kb = 0; kb < 8; kb++) {
        const int cur = kb & 1, nxt = cur ^ 1;

        if (kb < 7) {   // next stage's global loads, hidden under compute
            const float* ap = aptr + ((kb + 1) << 5);
            va[0] = *reinterpret_cast<const float4*>(ap);
            va[1] = *reinterpret_cast<const float4*>(ap + 4);
            const float* bp = bptr + (u64)((kb + 1) << 5) * HH;
            #pragma unroll
            for (int q = 0; q < 4; q++)
                vb[q] = *reinterpret_cast<const float4*>(bp + (q << 2));
        }

        #pragma unroll
        for (int k = 0; k < 32; k++) {
            float4 af = *reinterpret_cast<const float4*>(&As[cur][k][tyg << 2]);
            ulonglong2 b01 = *reinterpret_cast<const ulonglong2*>(&Bs[cur][k][txg << 3]);
            ulonglong2 b23 = *reinterpret_cast<const ulonglong2*>(&Bs[cur][k][(txg << 3) + 4]);
            u64 ad0 = dup2(af.x), ad1 = dup2(af.y), ad2 = dup2(af.z), ad3 = dup2(af.w);
            acc[0][0] = fma2(ad0, b01.x, acc[0][0]);
            acc[0][1] = fma2(ad0, b01.y, acc[0][1]);
            acc[0][2] = fma2(ad0, b23.x, acc[0][2]);
            acc[0][3] = fma2(ad0, b23.y, acc[0][3]);
            acc[1][0] = fma2(ad1, b01.x, acc[1][0]);
            acc[1][1] = fma2(ad1, b01.y, acc[1][1]);
            acc[1][2] = fma2(ad1, b23.x, acc[1][2]);
            acc[1][3] = fma2(ad1, b23.y, acc[1][3]);
            acc[2][0] = fma2(ad2, b01.x, acc[2][0]);
            acc[2][1] = fma2(ad2, b01.y, acc[2][1]);
            acc[2][2] = fma2(ad2, b23.x, acc[2][2]);
            acc[2][3] = fma2(ad2, b23.y, acc[2][3]);
            acc[3][0] = fma2(ad3, b01.x, acc[3][0]);
            acc[3][1] = fma2(ad3, b01.y, acc[3][1]);
            acc[3][2] = fma2(ad3, b23.x, acc[3][2]);
            acc[3][3] = fma2(ad3, b23.y, acc[3][3]);
        }

        if (kb < 7) {   // store into the other buffer, then sync
            As[nxt][akq + 0][am] = va[0].x; As[nxt][akq + 1][am] = va[0].y;
            As[nxt][akq + 2][am] = va[0].z; As[nxt][akq + 3][am] = va[0].w;
            As[nxt][akq + 4][am] = va[1].x; As[nxt][akq + 5][am] = va[1].y;
            As[nxt][akq + 6][am] = va[1].z; As[nxt][akq + 7][am] = va[1].w;
            #pragma unroll
            for (int q = 0; q < 4; q++)
                *reinterpret_cast<float4*>(&Bs[nxt][brow][bc + (q << 2)]) = vb[q];
            __syncthreads();
        }
    }

    // epilogue: thread's n range contiguous: n0 + txg*8 .. +7
    float4 bvA = make_float4(0.f, 0.f, 0.f, 0.f);
    float4 bvB = make_float4(0.f, 0.f, 0.f, 0.f);
    if (isHo) {
        bvA = *reinterpret_cast<const float4*>(&b1[n0 + (txg << 3)]);
        bvB = *reinterpret_cast<const float4*>(&b1[n0 + (txg << 3) + 4]);
    }

    #pragma unroll
    for (int m = 0; m < 4; m++) {
        float2 p0 = *reinterpret_cast<float2*>(&acc[m][0]);
        float2 p1 = *reinterpret_cast<float2*>(&acc[m][1]);
        float2 p2 = *reinterpret_cast<float2*>(&acc[m][2]);
        float2 p3 = *reinterpret_cast<float2*>(&acc[m][3]);
        float4 r0 = make_float4(p0.x + bvA.x, p0.y + bvA.y, p1.x + bvA.z, p1.y + bvA.w);
        float4 r1 = make_float4(p2.x + bvB.x, p2.y + bvB.y, p3.x + bvB.z, p3.y + bvB.w);
        int r = m0 + (tyg << 2) + m;
        *reinterpret_cast<float4*>(&C[(u64)r * HH + n0 + (txg << 3)])     = r0;
        *reinterpret_cast<float4*>(&C[(u64)r * HH + n0 + (txg << 3) + 4]) = r1;
    }
}

// ---------------------------------------------------------------------------
// Per-row linear terms: ct[t] = 0.505*<ht[t],W2>, co[o] = 0.505*<ho[o],W2>+b2
// ---------------------------------------------------------------------------
__global__ __launch_bounds__(256) void reduce_kernel(
    const float* __restrict__ W2, const float* __restrict__ b2)
{
    int warp = (blockIdx.x * blockDim.x + threadIdx.x) >> 5;
    int lane = threadIdx.x & 31;
    const float* row;
    float* dst;
    float extra = 0.f;
    if (warp < TT) { row = g_ht + (u64)warp * HH; dst = g_ct + warp; }
    else { row = g_ho + (u64)(warp - TT) * HH; dst = g_co + (warp - TT); extra = b2[0]; }
    float s = 0.f;
    #pragma unroll
    for (int i = 0; i < 4; i++) {
        float4 v = *reinterpret_cast<const float4*>(&row[(lane + 32 * i) << 2]);
        float4 w = *reinterpret_cast<const float4*>(&W2[(lane + 32 * i) << 2]);
        s += v.x * w.x + v.y * w.y + v.z * w.z + v.w * w.w;
    }
    #pragma unroll
    for (int off = 16; off; off >>= 1) s += __shfl_xor_sync(0xffffffffu, s, off);
    if (lane == 0) *dst = 0.505f * s + extra;
}

// ---------------------------------------------------------------------------
// Pairwise kernel: out[t,o] = ct[t]+co[o] + sum_h |ht+ho| * (0.495*W2[h])
// 64x64 tile, 512 threads (4 warps/SMSP), micro 2t x 4o, packed f32x2 inner.
// ---------------------------------------------------------------------------
__global__ __launch_bounds__(512) void pair_kernel(
    const float* __restrict__ W2, float* __restrict__ out)
{
    __shared__ float4 sA[16][65];      // [hq][t]
    __shared__ float4 sB[16][65];      // [hq][o]
    __shared__ float4 sW[HH / 4];      // 0.495*W2 quads

    const int tid = threadIdx.x;
    const int tx = tid & 15;           // o lane (o = tx + 16j)
    const int ty = (tid >> 4) & 31;    // t lane (t = ty + 32i)
    const int t0 = blockIdx.y << 6;
    const int o0 = blockIdx.x << 6;

    if (tid < HH / 4) {
        float4 w = *reinterpret_cast<const float4*>(&W2[tid << 2]);
        w.x *= 0.495f; w.y *= 0.495f; w.z *= 0.495f; w.w *= 0.495f;
        sW[tid] = w;
    }

    u64 acc[2][4];
    #pragma unroll
    for (int i = 0; i < 2; i++)
        #pragma unroll
        for (int j = 0; j < 4; j++) acc[i][j] = 0ull;

    const int hs  = tid & 15;          // hq for staging
    const int ts2 = tid >> 4;          // 0..31
    const u64 SMASK = 0x7fffffff7fffffffULL;

    const float* pa0 = &g_ht[(u64)(t0 + ts2)      * HH + (hs << 2)];
    const float* pa1 = &g_ht[(u64)(t0 + ts2 + 32) * HH + (hs << 2)];
    const float* pb0 = &g_ho[(u64)(o0 + ts2)      * HH + (hs << 2)];
    const float* pb1 = &g_ho[(u64)(o0 + ts2 + 32) * HH + (hs << 2)];

    float4 va0 = *reinterpret_cast<const float4*>(pa0);
    float4 va1 = *reinterpret_cast<const float4*>(pa1);
    float4 vb0 = *reinterpret_cast<const float4*>(pb0);
    float4 vb1 = *reinterpret_cast<const float4*>(pb1);

    #pragma unroll 1
    for (int c = 0; c < 8; c++) {      // 8 chunks of 64 h
        __syncthreads();
        sA[hs][ts2] = va0; sA[hs][ts2 + 32] = va1;
        sB[hs][ts2] = vb0; sB[hs][ts2 + 32] = vb1;
        __syncthreads();

        if (c < 7) {                   // prefetch next chunk under compute
            int off = (c + 1) << 6;
            va0 = *reinterpret_cast<const float4*>(pa0 + off);
            va1 = *reinterpret_cast<const float4*>(pa1 + off);
            vb0 = *reinterpret_cast<const float4*>(pb0 + off);
            vb1 = *reinterpret_cast<const float4*>(pb1 + off);
        }

        #pragma unroll
        for (int hq = 0; hq < 16; hq++) {
            ulonglong2 w = *reinterpret_cast<const ulonglong2*>(&sW[(c << 4) + hq]);
            ulonglong2 a[2], b[4];
            #pragma unroll
            for (int i = 0; i < 2; i++)
                a[i] = *reinterpret_cast<const ulonglong2*>(&sA[hq][ty + (i << 5)]);
            #pragma unroll
            for (int j = 0; j < 4; j++)
                b[j] = *reinterpret_cast<const ulonglong2*>(&sB[hq][tx + (j << 4)]);
            #pragma unroll
            for (int i = 0; i < 2; i++)
                #pragma unroll
                for (int j = 0; j < 4; j++) {
                    u64 x = add2(a[i].x, b[j].x) & SMASK;
                    acc[i][j] = fma2(x, w.x, acc[i][j]);
                    u64 y = add2(a[i].y, b[j].y) & SMASK;
                    acc[i][j] = fma2(y, w.y, acc[i][j]);
                }
        }
    }

    float ctv[2], cov[4];
    #pragma unroll
    for (int i = 0; i < 2; i++) ctv[i] = g_ct[t0 + ty + (i << 5)];
    #pragma unroll
    for (int j = 0; j < 4; j++) cov[j] = g_co[o0 + tx + (j << 4)];
    #pragma unroll
    for (int i = 0; i < 2; i++)
        #pragma unroll
        for (int j = 0; j < 4; j++) {
            float2 p = *reinterpret_cast<float2*>(&acc[i][j]);
            out[(u64)(t0 + ty + (i << 5)) * OO + o0 + tx + (j << 4)]
                = ctv[i] + cov[j] + p.x + p.y;
        }
}

extern "C" void kernel_launch(void* const* d_in, const int* in_sizes, int n_in,
                              void* d_out, int out_size)
{
    const float* z_t = (const float*)d_in[0];   // [1024,256]
    const float* z_o = (const float*)d_in[1];   // [512,256]
    const float* W1  = (const float*)d_in[2];   // [512,512]
    const float* b1  = (const float*)d_in[3];   // [512]
    const float* W2  = (const float*)d_in[4];   // [512,1]
    const float* b2  = (const float*)d_in[5];   // [1]
    float* out = (float*)d_out;                 // [1024,512]

    gemm_kernel<<<dim3(4, 24), 256>>>(z_t, z_o, W1, b1);
    reduce_kernel<<<192, 256>>>(W2, b2);
    pair_kernel<<<dim3(OO / 64, TT / 64), 512>>>(W2, out);
}

// round 11
// speedup vs baseline: 1.1296x; 1.1296x over previous
#include <cuda_runtime.h>

#define TT 1024
#define OO 512
#define DD 256
#define HH 512

__device__ float g_ht[TT * HH];   // z_t @ W1[:D]            [1024,512]
__device__ float g_ho[OO * HH];   // z_o @ W1[D:] + b1       [512,512]
__device__ float g_ct[TT];        // 0.505 * <ht[t], W2>
__device__ float g_co[OO];        // 0.505 * <ho[o], W2> + b2

typedef unsigned long long u64;

__device__ __forceinline__ u64 add2(u64 a, u64 b) {
    u64 d; asm("add.rn.f32x2 %0,%1,%2;" : "=l"(d) : "l"(a), "l"(b)); return d;
}
__device__ __forceinline__ u64 fma2(u64 a, u64 b, u64 c) {
    u64 d; asm("fma.rn.f32x2 %0,%1,%2,%3;" : "=l"(d) : "l"(a), "l"(b), "l"(c)); return d;
}
__device__ __forceinline__ u64 dup2(float v) {
    u64 d; asm("mov.b64 %0,{%1,%1};" : "=l"(d) : "f"(v)); return d;
}

// ---------------------------------------------------------------------------
// Fused GEMM over combined M=1536: rows [0,1024)=z_t@W1[:D],
// [1024,1536)=z_o@W1[D:]+b1.
// BM=64, BN=32, BK=32, 128 threads, micro 4m x 4n. Grid (16,24)=384 CTAs.
// Inner loop MANUALLY SOFTWARE-PIPELINED depth-2: smem->reg loads for k+2
// issued while computing k, so the 29-cyc LDS latency is covered by two
// 16-cyc fma bodies. Loads are phase-aligned conflict-free:
//   a: LDS.128 at As[k][ty*4] (4 distinct 16B, broadcast)
//   b: LDS.128 at Bs[k][tx*4] (lanes 0-7 cover 128B contiguous)
// Double-buffered smem, 1 syncthreads per 32-k block.
// ---------------------------------------------------------------------------
__global__ __launch_bounds__(128) void gemm_kernel(
    const float* __restrict__ z_t, const float* __restrict__ z_o,
    const float* __restrict__ W1,  const float* __restrict__ b1)
{
    __shared__ float As[2][32][68];   // [buf][k][m]; 272B row (16B mult)
    __shared__ float Bs[2][32][36];   // [buf][k][n]; 144B row (16B mult)

    const int tid = threadIdx.x;
    const int mt  = blockIdx.y;             // 0..23
    const int n0  = blockIdx.x << 5;        // 0..480
    const bool isHo = (mt >= 16);
    const int m0 = (isHo ? (mt - 16) : mt) << 6;
    const float* A = isHo ? z_o : z_t;
    const float* B = isHo ? (W1 + (u64)DD * HH) : W1;
    float* C = isHo ? g_ho : g_ht;

    // A staging: m = tid&63, k-half = (tid>>6)*16, 4 float4 along k
    const int am  = tid & 63;
    const int akh = (tid >> 6) << 4;        // 0 or 16
    // B staging: k row = tid>>2 (0..31), n base = (tid&3)*8, 2 float4
    const int bk = tid >> 2;
    const int bn = (tid & 3) << 3;

    // compute: n quad at tx*4, m quad at ty*4
    const int tx = tid & 7;
    const int ty = tid >> 3;                // 0..15

    u64 acc[4][2];
    #pragma unroll
    for (int m = 0; m < 4; m++) { acc[m][0] = 0ull; acc[m][1] = 0ull; }

    const float* aptr = &A[(u64)(m0 + am) * DD + akh];
    const float* bptr = &B[(u64)bk * HH + n0 + bn];

    float4 va[4], vb[2];

    // ---- prologue: stage 0 ----
    #pragma unroll
    for (int q = 0; q < 4; q++)
        va[q] = *reinterpret_cast<const float4*>(aptr + (q << 2));
    vb[0] = *reinterpret_cast<const float4*>(bptr);
    vb[1] = *reinterpret_cast<const float4*>(bptr + 4);

    #pragma unroll
    for (int q = 0; q < 4; q++) {
        As[0][akh + (q << 2) + 0][am] = va[q].x;
        As[0][akh + (q << 2) + 1][am] = va[q].y;
        As[0][akh + (q << 2) + 2][am] = va[q].z;
        As[0][akh + (q << 2) + 3][am] = va[q].w;
    }
    *reinterpret_cast<float4*>(&Bs[0][bk][bn])     = vb[0];
    *reinterpret_cast<float4*>(&Bs[0][bk][bn + 4]) = vb[1];
    __syncthreads();

    #pragma unroll 1
    for (int kb = 0; kb < 8; kb++) {
        const int cur = kb & 1, nxt = cur ^ 1;

        if (kb < 7) {   // next stage's global loads, hidden under compute
            const float* ap = aptr + ((kb + 1) << 5);
            #pragma unroll
            for (int q = 0; q < 4; q++)
                va[q] = *reinterpret_cast<const float4*>(ap + (q << 2));
            const float* bp = bptr + (u64)((kb + 1) << 5) * HH;
            vb[0] = *reinterpret_cast<const float4*>(bp);
            vb[1] = *reinterpret_cast<const float4*>(bp + 4);
        }

        // ---- depth-2 pipelined 32-k compute ----
        float4     a0 = *reinterpret_cast<const float4*>(&As[cur][0][ty << 2]);
        ulonglong2 q0 = *reinterpret_cast<const ulonglong2*>(&Bs[cur][0][tx << 2]);
        float4     a1 = *reinterpret_cast<const float4*>(&As[cur][1][ty << 2]);
        ulonglong2 q1 = *reinterpret_cast<const ulonglong2*>(&Bs[cur][1][tx << 2]);

        #pragma unroll
        for (int k = 0; k < 32; k++) {
            float4 a2; ulonglong2 q2;
            if (k < 30) {
                a2 = *reinterpret_cast<const float4*>(&As[cur][k + 2][ty << 2]);
                q2 = *reinterpret_cast<const ulonglong2*>(&Bs[cur][k + 2][tx << 2]);
            }
            u64 ad0 = dup2(a0.x), ad1 = dup2(a0.y), ad2 = dup2(a0.z), ad3 = dup2(a0.w);
            acc[0][0] = fma2(ad0, q0.x, acc[0][0]);
            acc[0][1] = fma2(ad0, q0.y, acc[0][1]);
            acc[1][0] = fma2(ad1, q0.x, acc[1][0]);
            acc[1][1] = fma2(ad1, q0.y, acc[1][1]);
            acc[2][0] = fma2(ad2, q0.x, acc[2][0]);
            acc[2][1] = fma2(ad2, q0.y, acc[2][1]);
            acc[3][0] = fma2(ad3, q0.x, acc[3][0]);
            acc[3][1] = fma2(ad3, q0.y, acc[3][1]);
            a0 = a1; q0 = q1;
            a1 = a2; q1 = q2;
        }

        if (kb < 7) {   // store into the other buffer, then sync
            #pragma unroll
            for (int q = 0; q < 4; q++) {
                As[nxt][akh + (q << 2) + 0][am] = va[q].x;
                As[nxt][akh + (q << 2) + 1][am] = va[q].y;
                As[nxt][akh + (q << 2) + 2][am] = va[q].z;
                As[nxt][akh + (q << 2) + 3][am] = va[q].w;
            }
            *reinterpret_cast<float4*>(&Bs[nxt][bk][bn])     = vb[0];
            *reinterpret_cast<float4*>(&Bs[nxt][bk][bn + 4]) = vb[1];
            __syncthreads();
        }
    }

    // epilogue: thread covers m0+ty*4..+3, n0+tx*4..+3
    float4 bv = make_float4(0.f, 0.f, 0.f, 0.f);
    if (isHo) bv = *reinterpret_cast<const float4*>(&b1[n0 + (tx << 2)]);

    #pragma unroll
    for (int m = 0; m < 4; m++) {
        float2 p0 = *reinterpret_cast<float2*>(&acc[m][0]);
        float2 p1 = *reinterpret_cast<float2*>(&acc[m][1]);
        float4 r = make_float4(p0.x + bv.x, p0.y + bv.y, p1.x + bv.z, p1.y + bv.w);
        int row = m0 + (ty << 2) + m;
        *reinterpret_cast<float4*>(&C[(u64)row * HH + n0 + (tx << 2)]) = r;
    }
}

// ---------------------------------------------------------------------------
// Per-row linear terms: ct[t] = 0.505*<ht[t],W2>, co[o] = 0.505*<ho[o],W2>+b2
// ---------------------------------------------------------------------------
__global__ __launch_bounds__(256) void reduce_kernel(
    const float* __restrict__ W2, const float* __restrict__ b2)
{
    int warp = (blockIdx.x * blockDim.x + threadIdx.x) >> 5;
    int lane = threadIdx.x & 31;
    const float* row;
    float* dst;
    float extra = 0.f;
    if (warp < TT) { row = g_ht + (u64)warp * HH; dst = g_ct + warp; }
    else { row = g_ho + (u64)(warp - TT) * HH; dst = g_co + (warp - TT); extra = b2[0]; }
    float s = 0.f;
    #pragma unroll
    for (int i = 0; i < 4; i++) {
        float4 v = *reinterpret_cast<const float4*>(&row[(lane + 32 * i) << 2]);
        float4 w = *reinterpret_cast<const float4*>(&W2[(lane + 32 * i) << 2]);
        s += v.x * w.x + v.y * w.y + v.z * w.z + v.w * w.w;
    }
    #pragma unroll
    for (int off = 16; off; off >>= 1) s += __shfl_xor_sync(0xffffffffu, s, off);
    if (lane == 0) *dst = 0.505f * s + extra;
}

// ---------------------------------------------------------------------------
// Pairwise kernel: out[t,o] = ct[t]+co[o] + sum_h |ht+ho| * (0.495*W2[h])
// 64x64 tile, 512 threads (4 warps/SMSP), micro 2t x 4o, packed f32x2 inner.
// ---------------------------------------------------------------------------
__global__ __launch_bounds__(512) void pair_kernel(
    const float* __restrict__ W2, float* __restrict__ out)
{
    __shared__ float4 sA[16][65];      // [hq][t]
    __shared__ float4 sB[16][65];      // [hq][o]
    __shared__ float4 sW[HH / 4];      // 0.495*W2 quads

    const int tid = threadIdx.x;
    const int tx = tid & 15;           // o lane (o = tx + 16j)
    const int ty = (tid >> 4) & 31;    // t lane (t = ty + 32i)
    const int t0 = blockIdx.y << 6;
    const int o0 = blockIdx.x << 6;

    if (tid < HH / 4) {
        float4 w = *reinterpret_cast<const float4*>(&W2[tid << 2]);
        w.x *= 0.495f; w.y *= 0.495f; w.z *= 0.495f; w.w *= 0.495f;
        sW[tid] = w;
    }

    u64 acc[2][4];
    #pragma unroll
    for (int i = 0; i < 2; i++)
        #pragma unroll
        for (int j = 0; j < 4; j++) acc[i][j] = 0ull;

    const int hs  = tid & 15;          // hq for staging
    const int ts2 = tid >> 4;          // 0..31
    const u64 SMASK = 0x7fffffff7fffffffULL;

    const float* pa0 = &g_ht[(u64)(t0 + ts2)      * HH + (hs << 2)];
    const float* pa1 = &g_ht[(u64)(t0 + ts2 + 32) * HH + (hs << 2)];
    const float* pb0 = &g_ho[(u64)(o0 + ts2)      * HH + (hs << 2)];
    const float* pb1 = &g_ho[(u64)(o0 + ts2 + 32) * HH + (hs << 2)];

    float4 va0 = *reinterpret_cast<const float4*>(pa0);
    float4 va1 = *reinterpret_cast<const float4*>(pa1);
    float4 vb0 = *reinterpret_cast<const float4*>(pb0);
    float4 vb1 = *reinterpret_cast<const float4*>(pb1);

    #pragma unroll 1
    for (int c = 0; c < 8; c++) {      // 8 chunks of 64 h
        __syncthreads();
        sA[hs][ts2] = va0; sA[hs][ts2 + 32] = va1;
        sB[hs][ts2] = vb0; sB[hs][ts2 + 32] = vb1;
        __syncthreads();

        if (c < 7) {                   // prefetch next chunk under compute
            int off = (c + 1) << 6;
            va0 = *reinterpret_cast<const float4*>(pa0 + off);
            va1 = *reinterpret_cast<const float4*>(pa1 + off);
            vb0 = *reinterpret_cast<const float4*>(pb0 + off);
            vb1 = *reinterpret_cast<const float4*>(pb1 + off);
        }

        #pragma unroll
        for (int hq = 0; hq < 16; hq++) {
            ulonglong2 w = *reinterpret_cast<const ulonglong2*>(&sW[(c << 4) + hq]);
            ulonglong2 a[2], b[4];
            #pragma unroll
            for (int i = 0; i < 2; i++)
                a[i] = *reinterpret_cast<const ulonglong2*>(&sA[hq][ty + (i << 5)]);
            #pragma unroll
            for (int j = 0; j < 4; j++)
                b[j] = *reinterpret_cast<const ulonglong2*>(&sB[hq][tx + (j << 4)]);
            #pragma unroll
            for (int i = 0; i < 2; i++)
                #pragma unroll
                for (int j = 0; j < 4; j++) {
                    u64 x = add2(a[i].x, b[j].x) & SMASK;
                    acc[i][j] = fma2(x, w.x, acc[i][j]);
                    u64 y = add2(a[i].y, b[j].y) & SMASK;
                    acc[i][j] = fma2(y, w.y, acc[i][j]);
                }
        }
    }

    float ctv[2], cov[4];
    #pragma unroll
    for (int i = 0; i < 2; i++) ctv[i] = g_ct[t0 + ty + (i << 5)];
    #pragma unroll
    for (int j = 0; j < 4; j++) cov[j] = g_co[o0 + tx + (j << 4)];
    #pragma unroll
    for (int i = 0; i < 2; i++)
        #pragma unroll
        for (int j = 0; j < 4; j++) {
            float2 p = *reinterpret_cast<float2*>(&acc[i][j]);
            out[(u64)(t0 + ty + (i << 5)) * OO + o0 + tx + (j << 4)]
                = ctv[i] + cov[j] + p.x + p.y;
        }
}

extern "C" void kernel_launch(void* const* d_in, const int* in_sizes, int n_in,
                              void* d_out, int out_size)
{
    const float* z_t = (const float*)d_in[0];   // [1024,256]
    const float* z_o = (const float*)d_in[1];   // [512,256]
    const float* W1  = (const float*)d_in[2];   // [512,512]
    const float* b1  = (const float*)d_in[3];   // [512]
    const float* W2  = (const float*)d_in[4];   // [512,1]
    const float* b2  = (const float*)d_in[5];   // [1]
    float* out = (float*)d_out;                 // [1024,512]

    gemm_kernel<<<dim3(16, 24), 128>>>(z_t, z_o, W1, b1);
    reduce_kernel<<<192, 256>>>(W2, b2);
    pair_kernel<<<dim3(OO / 64, TT / 64), 512>>>(W2, out);
}